// round 9
// baseline (speedup 1.0000x reference)
#include <cuda_runtime.h>
#include <cstddef>

// Involution (B=8, H=W=192, C=64, G=4, K=3, R=4 -> cr=16)
// R9: R7 structure (128 thr, 16x16 tile, 2 vertical px/thread, channel-split
// smem tile, weights in __constant__) + packed f32x2 FFMA2 math everywhere.

#define HH 192
#define WW 192
#define CC 64
#define CR 16
#define TAPS 9

typedef unsigned long long u64;

constexpr int TILE = 16;
constexpr int HALO = 18;
constexpr int PSTR = 9;                               // f4 per pixel (8 data + 1 pad)
constexpr int TILE_F4 = HALO * HALO * PSTR;           // 2916
constexpr int SMEM_BYTES = TILE_F4 * 16;              // 46656 B

struct ConstPart {
    u64 w1p[16][8][4];   // [c4][dpair][cc]: packed {w1f[4c4+cc][2dp], w1f[4c4+cc][2dp+1]}, BN folded
    u64 w2p[144][2];     // [d*9+tap][0]={g0,g1}, [1]={g2,g3}
    u64 b2p[9][2];
    u64 b1p[8];          // packed BN-folded bias pairs
};
__constant__ ConstPart cW;
__device__ ConstPart scratchW;

__device__ __forceinline__ u64 pack2(float a, float b) {
    u64 r; asm("mov.b64 %0, {%1, %2};" : "=l"(r) : "f"(a), "f"(b)); return r;
}
__device__ __forceinline__ u64 dup2(float v) {
    u64 r; asm("mov.b64 %0, {%1, %1};" : "=l"(r) : "f"(v)); return r;
}
__device__ __forceinline__ float2 unpk(u64 p) {
    float2 f; asm("mov.b64 {%0, %1}, %2;" : "=f"(f.x), "=f"(f.y) : "l"(p)); return f;
}
__device__ __forceinline__ u64 fma2(u64 a, u64 b, u64 c) {
    u64 r; asm("fma.rn.f32x2 %0, %1, %2, %3;" : "=l"(r) : "l"(a), "l"(b), "l"(c)); return r;
}

__global__ void involution_prep_kernel(const float* __restrict__ w1,
                                       const float* __restrict__ b1,
                                       const float* __restrict__ gamma,
                                       const float* __restrict__ beta,
                                       const float* __restrict__ mean,
                                       const float* __restrict__ var,
                                       const float* __restrict__ w2,
                                       const float* __restrict__ b2) {
    __shared__ float s[16];
    int tid = threadIdx.x;   // 256 threads
    if (tid < 16) {
        float sc = gamma[tid] * rsqrtf(var[tid] + 1e-3f);
        s[tid] = sc;
    }
    __syncthreads();
    if (tid < 8) {
        float a = (b1[2 * tid]     - mean[2 * tid])     * s[2 * tid]     + beta[2 * tid];
        float b = (b1[2 * tid + 1] - mean[2 * tid + 1]) * s[2 * tid + 1] + beta[2 * tid + 1];
        scratchW.b1p[tid] = pack2(a, b);
    }
    // w1p: 512 entries
    for (int i = tid; i < 512; i += 256) {
        int c4 = i >> 5;
        int dp = (i >> 2) & 7;
        int cc = i & 3;
        int c  = 4 * c4 + cc;
        float a = w1[c * CR + 2 * dp]     * s[2 * dp];
        float b = w1[c * CR + 2 * dp + 1] * s[2 * dp + 1];
        scratchW.w1p[c4][dp][cc] = pack2(a, b);
    }
    if (tid < 144) {
        float4 v = ((const float4*)w2)[tid];
        scratchW.w2p[tid][0] = pack2(v.x, v.y);
        scratchW.w2p[tid][1] = pack2(v.z, v.w);
    }
    if (tid < 9) {
        float4 v = ((const float4*)b2)[tid];
        scratchW.b2p[tid][0] = pack2(v.x, v.y);
        scratchW.b2p[tid][1] = pack2(v.z, v.w);
    }
}

__global__ __launch_bounds__(128, 4)
void involution_fused_kernel(const float* __restrict__ x,
                             float* __restrict__ out) {
    extern __shared__ float4 tile4[];         // [18*18 px][9 f4]

    const int tid = threadIdx.x;              // 0..127
    const int tx  = tid & 15;
    const int tyy = tid >> 4;                 // 0..7 -> output rows 2*tyy, 2*tyy+1
    const int gx0 = blockIdx.x * TILE;
    const int gy0 = blockIdx.y * TILE;
    const int bz  = blockIdx.z;

    const float* xb = x + (size_t)bz * ((size_t)HH * WW * CC);

    // ---- load tile channel-half u0-7 (zero-padded SAME) ----
    #pragma unroll 2
    for (int s = tid; s < HALO * HALO * 8; s += 128) {
        int u   = s & 7;
        int pix = s >> 3;
        int py  = pix / HALO;
        int px  = pix - py * HALO;
        int gh  = gy0 - 1 + py;
        int gw  = gx0 - 1 + px;
        float4 v = make_float4(0.f, 0.f, 0.f, 0.f);
        if ((unsigned)gh < HH && (unsigned)gw < WW)
            v = ((const float4*)(xb + ((size_t)gh * WW + gw) * CC))[u];
        tile4[pix * PSTR + u] = v;
    }
    __syncthreads();

    // ---- phase B: t_p = relu(x_p . w1' + b1'), packed pairs over d ----
    const int pc0 = (2 * tyy + 1) * HALO + (tx + 1);
    const int pc1 = pc0 + HALO;
    const float4* g0 = (const float4*)(xb + ((size_t)(gy0 + 2 * tyy)     * WW + gx0 + tx) * CC);
    const float4* g1 = (const float4*)(xb + ((size_t)(gy0 + 2 * tyy + 1) * WW + gx0 + tx) * CC);

    u64 t20[8], t21[8];
    #pragma unroll
    for (int dp = 0; dp < 8; dp++) { t20[dp] = cW.b1p[dp]; t21[dp] = cW.b1p[dp]; }

    const float4* xc0 = tile4 + pc0 * PSTR;
    const float4* xc1 = tile4 + pc1 * PSTR;
    #pragma unroll
    for (int c4 = 0; c4 < 8; c4++) {               // first channel half from smem
        float4 x0 = xc0[c4];
        float4 x1 = xc1[c4];
        u64 a0 = dup2(x0.x), a1 = dup2(x0.y), a2 = dup2(x0.z), a3 = dup2(x0.w);
        u64 b0 = dup2(x1.x), b1v = dup2(x1.y), b2v = dup2(x1.z), b3 = dup2(x1.w);
        #pragma unroll
        for (int dp = 0; dp < 8; dp++) {
            const u64* w = cW.w1p[c4][dp];
            t20[dp] = fma2(a0, w[0], t20[dp]);
            t20[dp] = fma2(a1, w[1], t20[dp]);
            t20[dp] = fma2(a2, w[2], t20[dp]);
            t20[dp] = fma2(a3, w[3], t20[dp]);
            t21[dp] = fma2(b0, w[0], t21[dp]);
            t21[dp] = fma2(b1v, w[1], t21[dp]);
            t21[dp] = fma2(b2v, w[2], t21[dp]);
            t21[dp] = fma2(b3, w[3], t21[dp]);
        }
    }
    #pragma unroll
    for (int c4 = 8; c4 < 16; c4++) {              // second channel half from global
        float4 x0 = g0[c4];
        float4 x1 = g1[c4];
        u64 a0 = dup2(x0.x), a1 = dup2(x0.y), a2 = dup2(x0.z), a3 = dup2(x0.w);
        u64 b0 = dup2(x1.x), b1v = dup2(x1.y), b2v = dup2(x1.z), b3 = dup2(x1.w);
        #pragma unroll
        for (int dp = 0; dp < 8; dp++) {
            const u64* w = cW.w1p[c4][dp];
            t20[dp] = fma2(a0, w[0], t20[dp]);
            t20[dp] = fma2(a1, w[1], t20[dp]);
            t20[dp] = fma2(a2, w[2], t20[dp]);
            t20[dp] = fma2(a3, w[3], t20[dp]);
            t21[dp] = fma2(b0, w[0], t21[dp]);
            t21[dp] = fma2(b1v, w[1], t21[dp]);
            t21[dp] = fma2(b2v, w[2], t21[dp]);
            t21[dp] = fma2(b3, w[3], t21[dp]);
        }
    }

    // unpack + relu
    float t0[CR], t1[CR];
    #pragma unroll
    for (int dp = 0; dp < 8; dp++) {
        float2 f0 = unpk(t20[dp]);
        float2 f1 = unpk(t21[dp]);
        t0[2 * dp]     = fmaxf(f0.x, 0.f);
        t0[2 * dp + 1] = fmaxf(f0.y, 0.f);
        t1[2 * dp]     = fmaxf(f1.x, 0.f);
        t1[2 * dp + 1] = fmaxf(f1.y, 0.f);
    }

    // ---- phase C: per-pixel 3x3 kernels, packed over group pairs ----
    u64 k0lo[TAPS], k0hi[TAPS], k1lo[TAPS], k1hi[TAPS];
    #pragma unroll
    for (int tap = 0; tap < TAPS; tap++) {
        k0lo[tap] = cW.b2p[tap][0]; k0hi[tap] = cW.b2p[tap][1];
        k1lo[tap] = cW.b2p[tap][0]; k1hi[tap] = cW.b2p[tap][1];
    }
    #pragma unroll
    for (int d = 0; d < CR; d++) {
        u64 a = dup2(t0[d]);
        u64 b = dup2(t1[d]);
        #pragma unroll
        for (int tap = 0; tap < TAPS; tap++) {
            const u64* w = cW.w2p[d * TAPS + tap];
            k0lo[tap] = fma2(a, w[0], k0lo[tap]);
            k0hi[tap] = fma2(a, w[1], k0hi[tap]);
            k1lo[tap] = fma2(b, w[0], k1lo[tap]);
            k1hi[tap] = fma2(b, w[1], k1hi[tap]);
        }
    }

    // ---- phase D: two channel-half passes; 4 smem rows serve 2 outputs ----
    float* o0 = out + (((size_t)bz * HH + gy0 + 2 * tyy)     * WW + gx0 + tx) * CC;
    float* o1 = out + (((size_t)bz * HH + gy0 + 2 * tyy + 1) * WW + gx0 + tx) * CC;
    const int rowstep = HALO * PSTR;
    const float4* base = tile4 + (2 * tyy * HALO + tx) * PSTR;

    #pragma unroll
    for (int uh = 0; uh < 2; uh++) {
        if (uh) {
            __syncthreads();
            #pragma unroll 2
            for (int s = tid; s < HALO * HALO * 8; s += 128) {
                int u   = s & 7;
                int pix = s >> 3;
                int py  = pix / HALO;
                int px  = pix - py * HALO;
                int gh  = gy0 - 1 + py;
                int gw  = gx0 - 1 + px;
                float4 v = make_float4(0.f, 0.f, 0.f, 0.f);
                if ((unsigned)gh < HH && (unsigned)gw < WW)
                    v = ((const float4*)(xb + ((size_t)gh * WW + gw) * CC))[8 + u];
                tile4[pix * PSTR + u] = v;
            }
            __syncthreads();
        }
        #pragma unroll 2
        for (int u = 0; u < 8; u++) {
            u64 s0lo = 0, s0hi = 0, s1lo = 0, s1hi = 0;  // 0x0 == {0.f,0.f}
            #pragma unroll
            for (int dj = 0; dj < 3; dj++) {
                const float4* col = base + dj * PSTR + u;
                ulonglong2 r0 = *(const ulonglong2*)(col);
                ulonglong2 r1 = *(const ulonglong2*)(col + rowstep);
                ulonglong2 r2 = *(const ulonglong2*)(col + 2 * rowstep);
                ulonglong2 r3 = *(const ulonglong2*)(col + 3 * rowstep);
                s0lo = fma2(k0lo[dj],     r0.x, s0lo); s0hi = fma2(k0hi[dj],     r0.y, s0hi);
                s0lo = fma2(k0lo[3 + dj], r1.x, s0lo); s0hi = fma2(k0hi[3 + dj], r1.y, s0hi);
                s0lo = fma2(k0lo[6 + dj], r2.x, s0lo); s0hi = fma2(k0hi[6 + dj], r2.y, s0hi);
                s1lo = fma2(k1lo[dj],     r1.x, s1lo); s1hi = fma2(k1hi[dj],     r1.y, s1hi);
                s1lo = fma2(k1lo[3 + dj], r2.x, s1lo); s1hi = fma2(k1hi[3 + dj], r2.y, s1hi);
                s1lo = fma2(k1lo[6 + dj], r3.x, s1lo); s1hi = fma2(k1hi[6 + dj], r3.y, s1hi);
            }
            ulonglong2 v0, v1;
            v0.x = s0lo; v0.y = s0hi;
            v1.x = s1lo; v1.y = s1hi;
            *(ulonglong2*)(o0 + (uh * 8 + u) * 4) = v0;
            *(ulonglong2*)(o1 + (uh * 8 + u) * 4) = v1;
        }
    }
}

extern "C" void kernel_launch(void* const* d_in, const int* in_sizes, int n_in,
                              void* d_out, int out_size) {
    const float* x     = (const float*)d_in[0];
    const float* w1    = (const float*)d_in[1];
    const float* b1    = (const float*)d_in[2];
    const float* gamma = (const float*)d_in[3];
    const float* beta  = (const float*)d_in[4];
    const float* mean  = (const float*)d_in[5];
    const float* var   = (const float*)d_in[6];
    const float* w2    = (const float*)d_in[7];
    const float* b2    = (const float*)d_in[8];
    float* out = (float*)d_out;

    int B = in_sizes[0] / (HH * WW * CC);

    // 1) fold BN + pack weights into device scratch
    involution_prep_kernel<<<1, 256>>>(w1, b1, gamma, beta, mean, var, w2, b2);

    // 2) copy packed weights into __constant__ (D2D memcpy node, capturable)
    static void* scratch_addr = nullptr;
    if (!scratch_addr) cudaGetSymbolAddress(&scratch_addr, scratchW);
    cudaMemcpyToSymbolAsync(cW, scratch_addr, sizeof(ConstPart), 0,
                            cudaMemcpyDeviceToDevice, 0);

    // 3) main fused kernel
    static bool attr_set = false;
    if (!attr_set) {
        cudaFuncSetAttribute(involution_fused_kernel,
                             cudaFuncAttributeMaxDynamicSharedMemorySize, SMEM_BYTES);
        attr_set = true;
    }
    dim3 grid(WW / TILE, HH / TILE, B);   // 12 x 12 x 8
    dim3 block(128);
    involution_fused_kernel<<<grid, block, SMEM_BYTES>>>(x, out);
}

// round 10
// speedup vs baseline: 1.2968x; 1.2968x over previous
#include <cuda_runtime.h>
#include <cstddef>

// Involution (B=8, H=W=192, C=64, G=4, K=3, R=4 -> cr=16)
// R10: 128 thr, 16x16 tile, 2 vertical px/thread, FULL 16-f4 tile in smem
// (86KB, 2 blocks/SM), branch-free cp.async.cg tile load (zero-fill via
// src-size), weights in __constant__, single-pass phase D, no reg cap.

#define HH 192
#define WW 192
#define CC 64
#define CR 16
#define TAPS 9

constexpr int TILE = 16;
constexpr int HALO = 18;
constexpr int PSTR = 17;                              // f4 per pixel (16 data + 1 pad)
constexpr int TILE_F4 = HALO * HALO * PSTR;           // 5508
constexpr int SMEM_BYTES = TILE_F4 * 16;              // 88128 B

struct ConstW {
    float4 w1[256];   // [c4=16][d=16], BN folded
    float4 w2[144];   // [d=16][tap=9], f4 over 4 groups
    float4 b2[9];
    float  b1[16];    // BN-folded bias
};
__constant__ ConstW cW;
__device__ ConstW scratchW;

__global__ void involution_prep_kernel(const float* __restrict__ w1,
                                       const float* __restrict__ b1,
                                       const float* __restrict__ gamma,
                                       const float* __restrict__ beta,
                                       const float* __restrict__ mean,
                                       const float* __restrict__ var,
                                       const float* __restrict__ w2,
                                       const float* __restrict__ b2) {
    __shared__ float s[16];
    int tid = threadIdx.x;   // 256 threads
    if (tid < 16) {
        float sc = gamma[tid] * rsqrtf(var[tid] + 1e-3f);
        s[tid] = sc;
        scratchW.b1[tid] = (b1[tid] - mean[tid]) * sc + beta[tid];
    }
    __syncthreads();
    {
        int d  = tid & 15;
        int c4 = tid >> 4;
        float sc = s[d];
        scratchW.w1[tid] = make_float4(w1[(4 * c4 + 0) * CR + d] * sc,
                                       w1[(4 * c4 + 1) * CR + d] * sc,
                                       w1[(4 * c4 + 2) * CR + d] * sc,
                                       w1[(4 * c4 + 3) * CR + d] * sc);
    }
    if (tid < 144) scratchW.w2[tid] = ((const float4*)w2)[tid];
    if (tid < 9)   scratchW.b2[tid] = ((const float4*)b2)[tid];
}

__device__ __forceinline__ void fma4(float4& a, const float4& k, const float4& v) {
    a.x = fmaf(k.x, v.x, a.x);
    a.y = fmaf(k.y, v.y, a.y);
    a.z = fmaf(k.z, v.z, a.z);
    a.w = fmaf(k.w, v.w, a.w);
}

__device__ __forceinline__ void cp16(unsigned dst, const void* src, int sz) {
    asm volatile("cp.async.cg.shared.global [%0], [%1], 16, %2;"
                 :: "r"(dst), "l"(src), "r"(sz) : "memory");
}

__global__ __launch_bounds__(128)
void involution_fused_kernel(const float* __restrict__ x,
                             float* __restrict__ out) {
    extern __shared__ float4 tile4[];         // [18*18 px][17 f4]

    const int tid = threadIdx.x;              // 0..127
    const int tx  = tid & 15;
    const int tyy = tid >> 4;                 // 0..7 -> output rows 2*tyy, 2*tyy+1
    const int gx0 = blockIdx.x * TILE;
    const int gy0 = blockIdx.y * TILE;
    const int bz  = blockIdx.z;

    const float* xb = x + (size_t)bz * ((size_t)HH * WW * CC);
    unsigned smem_base = (unsigned)__cvta_generic_to_shared(tile4);

    // ---- full halo tile load: branch-free cp.async (zero-fill OOB) ----
    #pragma unroll 4
    for (int s = tid; s < HALO * HALO * 16; s += 128) {
        int u   = s & 15;
        int pix = s >> 4;
        int py  = pix / HALO;
        int px  = pix - py * HALO;
        int gh  = gy0 - 1 + py;
        int gw  = gx0 - 1 + px;
        bool ok = ((unsigned)gh < HH) && ((unsigned)gw < WW);
        const float4* src = (const float4*)(xb + ((size_t)(ok ? gh : 0) * WW + (ok ? gw : 0)) * CC) + u;
        cp16(smem_base + (unsigned)(pix * PSTR + u) * 16u, src, ok ? 16 : 0);
    }
    asm volatile("cp.async.commit_group;\n\tcp.async.wait_group 0;" ::: "memory");
    __syncthreads();

    // ---- phase B: t_p[d] = relu(x_p . w1' + b1'), two pixels, all from smem ----
    const int pc0 = (2 * tyy + 1) * HALO + (tx + 1);
    const int pc1 = pc0 + HALO;

    float t0[CR], t1[CR];
    #pragma unroll
    for (int d = 0; d < CR; d++) { t0[d] = cW.b1[d]; t1[d] = cW.b1[d]; }

    const float4* xc0 = tile4 + pc0 * PSTR;
    const float4* xc1 = tile4 + pc1 * PSTR;
    #pragma unroll
    for (int c4 = 0; c4 < 16; c4++) {
        float4 x0 = xc0[c4];
        float4 x1 = xc1[c4];
        #pragma unroll
        for (int d = 0; d < CR; d++) {
            float4 w = cW.w1[c4 * 16 + d];
            t0[d] = fmaf(x0.x, w.x, fmaf(x0.y, w.y, fmaf(x0.z, w.z, fmaf(x0.w, w.w, t0[d]))));
            t1[d] = fmaf(x1.x, w.x, fmaf(x1.y, w.y, fmaf(x1.z, w.z, fmaf(x1.w, w.w, t1[d]))));
        }
    }
    #pragma unroll
    for (int d = 0; d < CR; d++) { t0[d] = fmaxf(t0[d], 0.f); t1[d] = fmaxf(t1[d], 0.f); }

    // ---- phase C: per-pixel 3x3 kernels (f4 over groups) ----
    float4 k0[TAPS], k1[TAPS];
    #pragma unroll
    for (int tap = 0; tap < TAPS; tap++) { k0[tap] = cW.b2[tap]; k1[tap] = cW.b2[tap]; }
    #pragma unroll
    for (int d = 0; d < CR; d++) {
        float a = t0[d], b = t1[d];
        #pragma unroll
        for (int tap = 0; tap < TAPS; tap++) {
            float4 w = cW.w2[d * TAPS + tap];
            k0[tap].x = fmaf(a, w.x, k0[tap].x); k0[tap].y = fmaf(a, w.y, k0[tap].y);
            k0[tap].z = fmaf(a, w.z, k0[tap].z); k0[tap].w = fmaf(a, w.w, k0[tap].w);
            k1[tap].x = fmaf(b, w.x, k1[tap].x); k1[tap].y = fmaf(b, w.y, k1[tap].y);
            k1[tap].z = fmaf(b, w.z, k1[tap].z); k1[tap].w = fmaf(b, w.w, k1[tap].w);
        }
    }

    // ---- phase D: single pass over all 16 u; 4 smem rows serve 2 outputs ----
    float4* o0 = (float4*)(out + (((size_t)bz * HH + gy0 + 2 * tyy)     * WW + gx0 + tx) * CC);
    float4* o1 = (float4*)(out + (((size_t)bz * HH + gy0 + 2 * tyy + 1) * WW + gx0 + tx) * CC);
    const int rowstep = HALO * PSTR;
    const float4* base = tile4 + (2 * tyy * HALO + tx) * PSTR;

    #pragma unroll 4
    for (int u = 0; u < 16; u++) {
        float4 a0 = make_float4(0.f, 0.f, 0.f, 0.f);
        float4 a1 = make_float4(0.f, 0.f, 0.f, 0.f);
        #pragma unroll
        for (int dj = 0; dj < 3; dj++) {
            const float4* col = base + dj * PSTR + u;
            float4 r0 = col[0];
            float4 r1 = col[rowstep];
            float4 r2 = col[2 * rowstep];
            float4 r3 = col[3 * rowstep];
            fma4(a0, k0[dj],     r0);
            fma4(a0, k0[3 + dj], r1);
            fma4(a0, k0[6 + dj], r2);
            fma4(a1, k1[dj],     r1);
            fma4(a1, k1[3 + dj], r2);
            fma4(a1, k1[6 + dj], r3);
        }
        o0[u] = a0;
        o1[u] = a1;
    }
}

extern "C" void kernel_launch(void* const* d_in, const int* in_sizes, int n_in,
                              void* d_out, int out_size) {
    const float* x     = (const float*)d_in[0];
    const float* w1    = (const float*)d_in[1];
    const float* b1    = (const float*)d_in[2];
    const float* gamma = (const float*)d_in[3];
    const float* beta  = (const float*)d_in[4];
    const float* mean  = (const float*)d_in[5];
    const float* var   = (const float*)d_in[6];
    const float* w2    = (const float*)d_in[7];
    const float* b2    = (const float*)d_in[8];
    float* out = (float*)d_out;

    int B = in_sizes[0] / (HH * WW * CC);

    // 1) fold BN + stage weights into device scratch
    involution_prep_kernel<<<1, 256>>>(w1, b1, gamma, beta, mean, var, w2, b2);

    // 2) copy into __constant__ (D2D memcpy node, graph-capturable)
    static void* scratch_addr = nullptr;
    if (!scratch_addr) cudaGetSymbolAddress(&scratch_addr, scratchW);
    cudaMemcpyToSymbolAsync(cW, scratch_addr, sizeof(ConstW), 0,
                            cudaMemcpyDeviceToDevice, 0);

    // 3) main fused kernel
    static bool attr_set = false;
    if (!attr_set) {
        cudaFuncSetAttribute(involution_fused_kernel,
                             cudaFuncAttributeMaxDynamicSharedMemorySize, SMEM_BYTES);
        attr_set = true;
    }
    dim3 grid(WW / TILE, HH / TILE, B);   // 12 x 12 x 8
    dim3 block(128);
    involution_fused_kernel<<<grid, block, SMEM_BYTES>>>(x, out);
}